// round 16
// baseline (speedup 1.0000x reference)
#include <cuda_runtime.h>
#include <cstdint>

#define B_ 8
#define C_ 64
#define H_ 256
#define W_ 256
#define HW_ (H_ * W_)
#define TH 2                  // output rows per block
#define ROWS 4                // staged rows (with halo)
#define NS 4                  // ring buffers
#define ROWB (W_ * 4)         // 1024 bytes per smem row (dense)
#define BUFB (ROWS * ROWB)    // 4096 bytes per buffer
#define FULLMASK 0xffffffffu

__device__ __forceinline__ uint32_t smem_u32(const void* p) {
    return (uint32_t)__cvta_generic_to_shared(p);
}
__device__ __forceinline__ void mbar_init(uint32_t mb, uint32_t cnt) {
    asm volatile("mbarrier.init.shared.b64 [%0], %1;" :: "r"(mb), "r"(cnt) : "memory");
}
__device__ __forceinline__ void mbar_expect_tx(uint32_t mb, uint32_t bytes) {
    asm volatile("mbarrier.arrive.expect_tx.shared.b64 _, [%0], %1;"
                 :: "r"(mb), "r"(bytes) : "memory");
}
__device__ __forceinline__ void bulk_g2s(uint32_t dst, const void* src, uint32_t bytes, uint32_t mb) {
    asm volatile("cp.async.bulk.shared::cta.global.mbarrier::complete_tx::bytes [%0], [%1], %2, [%3];"
                 :: "r"(dst), "l"(src), "r"(bytes), "r"(mb) : "memory");
}
__device__ __forceinline__ void mbar_wait(uint32_t mb, uint32_t parity) {
    uint32_t done;
    asm volatile("{\n\t.reg .pred p;\n\t"
                 "mbarrier.try_wait.parity.acquire.cta.shared::cta.b64 p, [%1], %2;\n\t"
                 "selp.b32 %0, 1, 0, p;\n\t}"
                 : "=r"(done) : "r"(mb), "r"(parity) : "memory");
    if (!done) {
        asm volatile("{\n\t.reg .pred P1;\n\t"
                     "WL%=:\n\t"
                     "mbarrier.try_wait.parity.acquire.cta.shared::cta.b64 P1, [%0], %1, 0x989680;\n\t"
                     "@P1 bra.uni WD%=;\n\t"
                     "bra.uni WL%=;\n\t"
                     "WD%=:\n\t}"
                     :: "r"(mb), "r"(parity) : "memory");
    }
}

__global__ __launch_bounds__(256, 6)
void conv_attn_v16(const float* __restrict__ q, const float* __restrict__ k,
                   const float* __restrict__ v, float* __restrict__ out)
{
    __shared__ __align__(16) float ring[NS][ROWS][W_];
    __shared__ uint64_t mbar[NS];

    const int tid  = threadIdx.x;
    const int lane = tid & 31;
    const int x    = tid & 127;         // 128 groups of 2 px; warp = 64 contiguous px of one row
    const int y    = tid >> 7;          // output row 0..1
    const int w0   = x * 2;
    const int h0   = blockIdx.x * TH;
    const int b    = blockIdx.y;

    const size_t cb = (size_t)b * C_ * HW_;
    const float* qb = q + cb;
    const float* kb = k + cb;
    const float* vb = v + cb;
    float*       ob = out + cb;
    const int rowoff = (h0 + y) * W_ + w0;

    // staged rows r=0..3 map to hh = h0-1+r (block-uniform validity)
    const bool rv0 = (h0 > 0);          // r=0 (hh = h0-1)
    const bool rv3 = (h0 + 2 < H_);     // r=3 (hh = h0+2)
    const uint32_t txbytes = (uint32_t)(2 + (rv0 ? 1 : 0) + (rv3 ? 1 : 0)) * ROWB;

    // zero never-staged border rows once (one float per thread per buffer)
    if (!rv0) for (int n = 0; n < NS; n++) ring[n][0][tid] = 0.0f;
    if (!rv3) for (int n = 0; n < NS; n++) ring[n][3][tid] = 0.0f;

    const uint32_t ring_s = smem_u32(&ring[0][0][0]);
    const uint32_t mb0 = smem_u32(&mbar[0]);
    if (tid < NS) mbar_init(mb0 + tid * 8, 1);
    __syncthreads();

    // producer (tid 0): stage channel plane at `chan` (row h0 base) into buffer bi
    auto stage = [&](const float* chan, int bi) {
        const uint32_t mb = mb0 + bi * 8;
        mbar_expect_tx(mb, txbytes);
        const uint32_t dstb = ring_s + (uint32_t)bi * BUFB;
        #pragma unroll
        for (int r = 0; r < ROWS; r++) {
            if (r == 0 && !rv0) continue;
            if (r == 3 && !rv3) continue;
            bulk_g2s(dstb + (uint32_t)r * ROWB, chan + (r - 1) * W_, ROWB, mb);
        }
    };

    const bool el = (w0 > 0);
    const bool er = (w0 + 2 < W_);

    // read row base pointers (add buffer byte offset per channel)
    const char* rb0 = (const char*)ring + (uint32_t)(y * ROWB + w0 * 4);
    const char* rb1 = rb0 + ROWB;
    const char* rb2 = rb1 + ROWB;

    float s[2][9];
#pragma unroll
    for (int j = 0; j < 2; j++)
#pragma unroll
        for (int i = 0; i < 9; i++) s[j][i] = 0.0f;

    uint32_t phases = 0;

    // ================= Pass 1: scores =================
    if (tid == 0) {
        stage(kb + (size_t)h0 * W_, 0);
        stage(kb + HW_ + (size_t)h0 * W_, 1);
        stage(kb + 2 * (size_t)HW_ + (size_t)h0 * W_, 2);
    }

    const float* qp = qb + rowoff;
    float2 qcur = *reinterpret_cast<const float2*>(qp);
    const float* kstage = kb + 3 * (size_t)HW_ + (size_t)h0 * W_;

    int bo = 0;
#pragma unroll 1
    for (int c = 0; c < C_; c++) {
        const int bi = c & 3;
        mbar_wait(mb0 + bi * 8, (phases >> bi) & 1);
        phases ^= 1u << bi;
        __syncthreads();        // WAR: last iter's reads precede this iter's stage

        const float2 qnext = *reinterpret_cast<const float2*>(qp + ((c + 1 < C_) ? HW_ : 0));
        qp += HW_;

#pragma unroll
        for (int dy = 0; dy < 3; dy++) {
            const float* rp = (const float*)((dy == 0 ? rb0 : dy == 1 ? rb1 : rb2) + bo);
            const float2 m = *reinterpret_cast<const float2*>(rp);
            float lft = __shfl_up_sync(FULLMASK, m.y, 1);
            float rgt = __shfl_down_sync(FULLMASK, m.x, 1);
            if (lane == 0)  lft = el ? rp[-1] : 0.0f;
            if (lane == 31) rgt = er ? rp[2]  : 0.0f;

            s[0][dy*3+0] = fmaf(qcur.x, lft, s[0][dy*3+0]);
            s[0][dy*3+1] = fmaf(qcur.x, m.x, s[0][dy*3+1]);
            s[0][dy*3+2] = fmaf(qcur.x, m.y, s[0][dy*3+2]);
            s[1][dy*3+0] = fmaf(qcur.y, m.x, s[1][dy*3+0]);
            s[1][dy*3+1] = fmaf(qcur.y, m.y, s[1][dy*3+1]);
            s[1][dy*3+2] = fmaf(qcur.y, rgt, s[1][dy*3+2]);
        }

        if (tid == 0 && c + 3 < C_) stage(kstage, (c + 3) & 3);
        kstage += HW_;
        qcur = qnext;
        bo += BUFB; if (bo == NS * BUFB) bo = 0;
    }
    __syncthreads();            // protect ring before pass-2 staging overwrites it

    // ================= Softmax over 9 taps (OOB taps = score 0, zero-pad semantics) =================
#pragma unroll
    for (int j = 0; j < 2; j++) {
        float mx = s[j][0];
#pragma unroll
        for (int i = 1; i < 9; i++) mx = fmaxf(mx, s[j][i]);
        float sum = 0.0f;
#pragma unroll
        for (int i = 0; i < 9; i++) { s[j][i] = __expf(s[j][i] - mx); sum += s[j][i]; }
        const float inv = 1.0f / sum;
#pragma unroll
        for (int i = 0; i < 9; i++) s[j][i] *= inv;
    }

    // ================= Pass 2: weighted v sum =================
    if (tid == 0) {
        stage(vb + (size_t)h0 * W_, 0);
        stage(vb + HW_ + (size_t)h0 * W_, 1);
        stage(vb + 2 * (size_t)HW_ + (size_t)h0 * W_, 2);
    }

    const float* vstage = vb + 3 * (size_t)HW_ + (size_t)h0 * W_;
    float* op = ob + rowoff;

    bo = 0;
#pragma unroll 1
    for (int c = 0; c < C_; c++) {
        const int bi = c & 3;
        mbar_wait(mb0 + bi * 8, (phases >> bi) & 1);
        phases ^= 1u << bi;
        __syncthreads();

        float acc0 = 0.f, acc1 = 0.f;
#pragma unroll
        for (int dy = 0; dy < 3; dy++) {
            const float* rp = (const float*)((dy == 0 ? rb0 : dy == 1 ? rb1 : rb2) + bo);
            const float2 m = *reinterpret_cast<const float2*>(rp);
            float lft = __shfl_up_sync(FULLMASK, m.y, 1);
            float rgt = __shfl_down_sync(FULLMASK, m.x, 1);
            if (lane == 0)  lft = el ? rp[-1] : 0.0f;
            if (lane == 31) rgt = er ? rp[2]  : 0.0f;

            acc0 = fmaf(s[0][dy*3+0], lft, acc0);
            acc0 = fmaf(s[0][dy*3+1], m.x, acc0);
            acc0 = fmaf(s[0][dy*3+2], m.y, acc0);
            acc1 = fmaf(s[1][dy*3+0], m.x, acc1);
            acc1 = fmaf(s[1][dy*3+1], m.y, acc1);
            acc1 = fmaf(s[1][dy*3+2], rgt, acc1);
        }

        if (tid == 0 && c + 3 < C_) stage(vstage, (c + 3) & 3);
        vstage += HW_;

        float2 o; o.x = acc0; o.y = acc1;
        *reinterpret_cast<float2*>(op) = o;
        op += HW_;
        bo += BUFB; if (bo == NS * BUFB) bo = 0;
    }
}

extern "C" void kernel_launch(void* const* d_in, const int* in_sizes, int n_in,
                              void* d_out, int out_size)
{
    const float* q = (const float*)d_in[0];
    const float* k = (const float*)d_in[1];
    const float* v = (const float*)d_in[2];
    float* out = (float*)d_out;

    dim3 block(256);
    dim3 grid(H_ / TH, B_);     // 128 x 8 = 1024 blocks
    conv_attn_v16<<<grid, block>>>(q, k, v, out);
}

// round 17
// speedup vs baseline: 1.4100x; 1.4100x over previous
#include <cuda_runtime.h>
#include <cstdint>

#define B_ 8
#define C_ 64
#define H_ 256
#define W_ 256
#define HW_ (H_ * W_)
#define TH 4                   // output rows per block
#define ROWS 6                 // staged rows per channel (with halo)
#define NS 4                   // ring buffers (2 channels each)
#define ROWB (W_ * 4)          // 1024 bytes per smem row
#define CHB (ROWS * ROWB)      // 6144 bytes per channel plane
#define BUF2B (2 * CHB)        // 12288 bytes per ring buffer
#define FULLMASK 0xffffffffu

__device__ __forceinline__ uint32_t smem_u32(const void* p) {
    return (uint32_t)__cvta_generic_to_shared(p);
}
__device__ __forceinline__ void mbar_init(uint32_t mb, uint32_t cnt) {
    asm volatile("mbarrier.init.shared.b64 [%0], %1;" :: "r"(mb), "r"(cnt) : "memory");
}
__device__ __forceinline__ void mbar_expect_tx(uint32_t mb, uint32_t bytes) {
    asm volatile("mbarrier.arrive.expect_tx.shared.b64 _, [%0], %1;"
                 :: "r"(mb), "r"(bytes) : "memory");
}
__device__ __forceinline__ void bulk_g2s(uint32_t dst, const void* src, uint32_t bytes, uint32_t mb) {
    asm volatile("cp.async.bulk.shared::cta.global.mbarrier::complete_tx::bytes [%0], [%1], %2, [%3];"
                 :: "r"(dst), "l"(src), "r"(bytes), "r"(mb) : "memory");
}
__device__ __forceinline__ void mbar_wait(uint32_t mb, uint32_t parity) {
    uint32_t done;
    asm volatile("{\n\t.reg .pred p;\n\t"
                 "mbarrier.try_wait.parity.acquire.cta.shared::cta.b64 p, [%1], %2;\n\t"
                 "selp.b32 %0, 1, 0, p;\n\t}"
                 : "=r"(done) : "r"(mb), "r"(parity) : "memory");
    if (!done) {
        asm volatile("{\n\t.reg .pred P1;\n\t"
                     "WL%=:\n\t"
                     "mbarrier.try_wait.parity.acquire.cta.shared::cta.b64 P1, [%0], %1, 0x989680;\n\t"
                     "@P1 bra.uni WD%=;\n\t"
                     "bra.uni WL%=;\n\t"
                     "WD%=:\n\t}"
                     :: "r"(mb), "r"(parity) : "memory");
    }
}

__global__ __launch_bounds__(256, 4)
void conv_attn_v17(const float* __restrict__ q, const float* __restrict__ k,
                   const float* __restrict__ v, float* __restrict__ out)
{
    __shared__ __align__(16) float ring[NS][2][ROWS][W_];
    __shared__ uint64_t mbar[NS];

    const int tid  = threadIdx.x;
    const int lane = tid & 31;
    const int x    = tid & 63;          // 64 groups of 4 px; warp = 128 contiguous px of one row
    const int y    = tid >> 6;          // output row 0..3
    const int w0   = x * 4;
    const int h0   = blockIdx.x * TH;
    const int b    = blockIdx.y;

    const size_t cb = (size_t)b * C_ * HW_;
    const float* qb = q + cb;
    const float* kb = k + cb;
    const float* vb = v + cb;
    float*       ob = out + cb;
    const int rowoff = (h0 + y) * W_ + w0;

    // staged rows r=0..5 map to hh = h0-1+r (block-uniform validity)
    const bool rv0 = (h0 > 0);
    const bool rv5 = (h0 + 4 < H_);
    const uint32_t txbytes = 2u * (uint32_t)(4 + (rv0 ? 1 : 0) + (rv5 ? 1 : 0)) * ROWB;

    // zero never-staged border rows once (both channel halves, all buffers)
    if (!rv0) for (int n = 0; n < NS; n++) { ring[n][0][0][tid] = 0.0f; ring[n][1][0][tid] = 0.0f; }
    if (!rv5) for (int n = 0; n < NS; n++) { ring[n][0][5][tid] = 0.0f; ring[n][1][5][tid] = 0.0f; }

    const uint32_t ring_s = smem_u32(&ring[0][0][0][0]);
    const uint32_t mb0 = smem_u32(&mbar[0]);
    if (tid < NS) mbar_init(mb0 + tid * 8, 1);
    __syncthreads();

    // producer (tid 0): stage channel pair (2jp, 2jp+1) at plane base `chan` into buffer bi
    auto stage = [&](const float* chan, int bi) {
        const uint32_t mb = mb0 + bi * 8;
        mbar_expect_tx(mb, txbytes);
        const uint32_t dstb = ring_s + (uint32_t)bi * BUF2B;
        #pragma unroll
        for (int u = 0; u < 2; u++) {
            const float* cp = chan + (size_t)u * HW_;
            const uint32_t du = dstb + (uint32_t)u * CHB;
            #pragma unroll
            for (int r = 0; r < ROWS; r++) {
                if (r == 0 && !rv0) continue;
                if (r == 5 && !rv5) continue;
                bulk_g2s(du + (uint32_t)r * ROWB, cp + (r - 1) * W_, ROWB, mb);
            }
        }
    };

    const bool el = (w0 > 0);
    const bool er = (w0 + 4 < W_);

    // read row base pointers (add buffer/half byte offset per use)
    const char* rbase = (const char*)ring + (uint32_t)(y * ROWB + w0 * 4);

    float s[4][9];
#pragma unroll
    for (int j = 0; j < 4; j++)
#pragma unroll
        for (int i = 0; i < 9; i++) s[j][i] = 0.0f;

    // score accumulation for one channel plane at byte offset `off`
    auto accum = [&](uint32_t off, const float4& qv) {
        const float qa[4] = {qv.x, qv.y, qv.z, qv.w};
#pragma unroll
        for (int dy = 0; dy < 3; dy++) {
            const float* rp = (const float*)(rbase + off + (uint32_t)dy * ROWB);
            const float4 m = *reinterpret_cast<const float4*>(rp);
            float lft = __shfl_up_sync(FULLMASK, m.w, 1);
            float rgt = __shfl_down_sync(FULLMASK, m.x, 1);
            if (lane == 0)  lft = el ? rp[-1] : 0.0f;
            if (lane == 31) rgt = er ? rp[4]  : 0.0f;
            const float a[6] = {lft, m.x, m.y, m.z, m.w, rgt};
#pragma unroll
            for (int j = 0; j < 4; j++)
#pragma unroll
                for (int dx = 0; dx < 3; dx++)
                    s[j][dy * 3 + dx] = fmaf(qa[j], a[j + dx], s[j][dy * 3 + dx]);
        }
    };

    uint32_t phases = 0;

    // ================= Pass 1: scores =================
    if (tid == 0) {
        stage(kb + (size_t)h0 * W_, 0);                       // ch 0,1
        stage(kb + 2 * (size_t)HW_ + (size_t)h0 * W_, 1);     // ch 2,3
        stage(kb + 4 * (size_t)HW_ + (size_t)h0 * W_, 2);     // ch 4,5
    }

    const float* qp = qb + rowoff;
    const float* kstage = kb + 6 * (size_t)HW_ + (size_t)h0 * W_;

    uint32_t bo = 0;
#pragma unroll 1
    for (int jp = 0; jp < C_ / 2; jp++) {
        const int bi = jp & 3;
        mbar_wait(mb0 + bi * 8, (phases >> bi) & 1);
        phases ^= 1u << bi;
        __syncthreads();        // WAR: last iter's reads precede this iter's stage

        const float4 q0 = *reinterpret_cast<const float4*>(qp);
        const float4 q1 = *reinterpret_cast<const float4*>(qp + HW_);
        qp += 2 * HW_;

        accum(bo,       q0);
        accum(bo + CHB, q1);

        if (tid == 0 && jp + 3 < C_ / 2) stage(kstage, (jp + 3) & 3);
        kstage += 2 * HW_;
        bo += BUF2B; if (bo == NS * BUF2B) bo = 0;
    }
    __syncthreads();            // protect ring before pass-2 staging overwrites it

    // ================= Softmax over 9 taps (OOB taps = score 0, zero-pad semantics) =================
#pragma unroll
    for (int j = 0; j < 4; j++) {
        float mx = s[j][0];
#pragma unroll
        for (int i = 1; i < 9; i++) mx = fmaxf(mx, s[j][i]);
        float sum = 0.0f;
#pragma unroll
        for (int i = 0; i < 9; i++) { s[j][i] = __expf(s[j][i] - mx); sum += s[j][i]; }
        const float inv = 1.0f / sum;
#pragma unroll
        for (int i = 0; i < 9; i++) s[j][i] *= inv;
    }

    // weighted-v accumulation for one channel plane at byte offset `off`
    auto wsum = [&](uint32_t off, float acc[4]) {
#pragma unroll
        for (int dy = 0; dy < 3; dy++) {
            const float* rp = (const float*)(rbase + off + (uint32_t)dy * ROWB);
            const float4 m = *reinterpret_cast<const float4*>(rp);
            float lft = __shfl_up_sync(FULLMASK, m.w, 1);
            float rgt = __shfl_down_sync(FULLMASK, m.x, 1);
            if (lane == 0)  lft = el ? rp[-1] : 0.0f;
            if (lane == 31) rgt = er ? rp[4]  : 0.0f;
            const float a[6] = {lft, m.x, m.y, m.z, m.w, rgt};
#pragma unroll
            for (int j = 0; j < 4; j++)
#pragma unroll
                for (int dx = 0; dx < 3; dx++)
                    acc[j] = fmaf(s[j][dy * 3 + dx], a[j + dx], acc[j]);
        }
    };

    // ================= Pass 2: weighted v sum =================
    if (tid == 0) {
        stage(vb + (size_t)h0 * W_, 0);
        stage(vb + 2 * (size_t)HW_ + (size_t)h0 * W_, 1);
        stage(vb + 4 * (size_t)HW_ + (size_t)h0 * W_, 2);
    }

    const float* vstage = vb + 6 * (size_t)HW_ + (size_t)h0 * W_;
    float* op = ob + rowoff;

    bo = 0;
#pragma unroll 1
    for (int jp = 0; jp < C_ / 2; jp++) {
        const int bi = jp & 3;
        mbar_wait(mb0 + bi * 8, (phases >> bi) & 1);
        phases ^= 1u << bi;
        __syncthreads();

        float acc0[4] = {0.f, 0.f, 0.f, 0.f};
        float acc1[4] = {0.f, 0.f, 0.f, 0.f};
        wsum(bo,       acc0);
        wsum(bo + CHB, acc1);

        if (tid == 0 && jp + 3 < C_ / 2) stage(vstage, (jp + 3) & 3);
        vstage += 2 * HW_;

        float4 o0, o1;
        o0.x = acc0[0]; o0.y = acc0[1]; o0.z = acc0[2]; o0.w = acc0[3];
        o1.x = acc1[0]; o1.y = acc1[1]; o1.z = acc1[2]; o1.w = acc1[3];
        *reinterpret_cast<float4*>(op)        = o0;
        *reinterpret_cast<float4*>(op + HW_)  = o1;
        op += 2 * HW_;
        bo += BUF2B; if (bo == NS * BUF2B) bo = 0;
    }
}

extern "C" void kernel_launch(void* const* d_in, const int* in_sizes, int n_in,
                              void* d_out, int out_size)
{
    const float* q = (const float*)d_in[0];
    const float* k = (const float*)d_in[1];
    const float* v = (const float*)d_in[2];
    float* out = (float*)d_out;

    dim3 block(256);
    dim3 grid(H_ / TH, B_);     // 64 x 8 = 512 blocks
    conv_attn_v17<<<grid, block>>>(q, k, v, out);
}